// round 13
// baseline (speedup 1.0000x reference)
#include <cuda_runtime.h>
#include <cuda_fp16.h>
#include <cstdint>
#include <math.h>

// ---------------- problem constants ----------------
#define B_    2
#define CIN   64
#define COUT  64
#define DIN   64
#define DOUT  62
#define KTAPS 27
#define EPS_  1e-8f

#define NCHUNK 54                  // 27 taps x {x, dx}, K=64 each
#define A_BYTES 16384              // 128 m x 64 k fp16
#define B_BYTES 16384              // 128 n x 64 k fp16
#define STAGE   (A_BYTES + B_BYTES)   // 32768
#define NSTAGE  3
#define SMEM_DYN (NSTAGE * STAGE)     // 98304 per CTA -> 2 CTAs/SM
#define SDY_STRIDE 132                // padded row stride for dy-exchange

// ---------------- device scratch ----------------
__device__ float g_wnv[B_ * COUT * CIN * KTAPS];
__device__ float g_dwv[B_ * COUT * CIN * KTAPS];
// A tiles fp16, pre-swizzled [b][kind][tap] x (128 m x 64 k), row=128B,
// 16B-chunk c stored at c ^ (m&7)
__device__ __align__(16) __half g_Ah[B_ * 2 * KTAPS * 128 * 64];
// channel-last fp16 inputs [b][z][y][x][c] (row = 64 ch = 128B), + overread pad
__device__ __align__(16) __half g_xTh [B_ * DIN * DIN * DIN * CIN + 32768];
__device__ __align__(16) __half g_dxTh[B_ * DIN * DIN * DIN * CIN + 32768];

// ---------------- helpers ----------------
__device__ __forceinline__ uint32_t smem_u32(const void* p) {
    uint32_t a;
    asm("{ .reg .u64 t; cvta.to.shared.u64 t, %1; cvt.u32.u64 %0, t; }" : "=r"(a) : "l"(p));
    return a;
}
__device__ __forceinline__ void cp_async16(uint32_t dst, const void* src) {
    asm volatile("cp.async.cg.shared.global [%0], [%1], 16;" :: "r"(dst), "l"(src) : "memory");
}
#define LDMATRIX_X4(r0, r1, r2, r3, addr) \
    asm volatile("ldmatrix.sync.aligned.m8n8.x4.shared.b16 {%0,%1,%2,%3}, [%4];" \
        : "=r"(r0), "=r"(r1), "=r"(r2), "=r"(r3) : "r"(addr))

__device__ __forceinline__ void mma_f16(float* d, const uint32_t* a, const uint32_t* b2) {
    asm volatile(
        "mma.sync.aligned.m16n8k16.row.col.f32.f16.f16.f32 "
        "{%0,%1,%2,%3}, {%4,%5,%6,%7}, {%8,%9}, {%0,%1,%2,%3};"
        : "+f"(d[0]), "+f"(d[1]), "+f"(d[2]), "+f"(d[3])
        : "r"(a[0]), "r"(a[1]), "r"(a[2]), "r"(a[3]), "r"(b2[0]), "r"(b2[1]));
}

// ---------------------------------------------------------------------------
// Prep: style modulation + demodulation (validated round 2)
// ---------------------------------------------------------------------------
__global__ void prep_kernel(const float* __restrict__ s,
                            const float* __restrict__ style_weight,
                            const float* __restrict__ style_bias,
                            const float* __restrict__ weight)
{
    __shared__ float wsm[CIN * KTAPS];
    __shared__ float dwsm[CIN * KTAPS];
    __shared__ float red0[256];
    __shared__ float red1[256];

    const int b  = blockIdx.x >> 6;
    const int co = blockIdx.x & 63;
    const int tid = threadIdx.x;

    const float s0 = s[b * 2 + 0];
    const float s1 = s[b * 2 + 1];

    float sw2 = 0.f, swd = 0.f;
    for (int e = tid; e < CIN * KTAPS; e += 256) {
        const int ci = e / KTAPS;
        const float smod  = s0 * style_weight[ci * 2 + 0]
                          + s1 * style_weight[ci * 2 + 1]
                          + style_bias[ci];
        const float dsmod = style_weight[ci * 2 + 1];
        const float wt = weight[(co * CIN) * KTAPS + e];
        const float wv = wt * smod;
        const float dv = wt * dsmod;
        wsm[e]  = wv;
        dwsm[e] = dv;
        sw2 += wv * wv;
        swd += wv * dv;
    }
    red0[tid] = sw2;
    red1[tid] = swd;
    __syncthreads();
    for (int st = 128; st > 0; st >>= 1) {
        if (tid < st) { red0[tid] += red0[tid + st]; red1[tid] += red1[tid + st]; }
        __syncthreads();
    }
    const float norm  = sqrtf(red0[0] + EPS_);
    const float inv   = 1.0f / norm;
    const float dnorm = -red1[0] * inv * inv * inv;

    const size_t ob = (size_t)(b * COUT + co) * (CIN * KTAPS);
    for (int e = tid; e < CIN * KTAPS; e += 256) {
        g_wnv[ob + e] = wsm[e] * inv;
        g_dwv[ob + e] = dwsm[e] * inv + wsm[e] * dnorm;
    }
}

// ---------------------------------------------------------------------------
// Pack A tiles: fp16, [m=128][k=64] rows of 128B; 16B chunk (k>>3) stored at
// (k>>3) ^ (m&7)  ->  ldmatrix conflict-free.
//   kind 0 (B = x):  m<64 -> wn[co=m],  m>=64 -> dw[co=m-64]
//   kind 1 (B = dx): m<64 -> 0,         m>=64 -> wn[co=m-64]
// ---------------------------------------------------------------------------
__global__ void pack_kernel()
{
    const int blk  = blockIdx.x;
    const int t    = blk % KTAPS;
    const int kind = (blk / KTAPS) & 1;
    const int b    = blk / (2 * KTAPS);
    char* dst = (char*)g_Ah + (size_t)blk * A_BYTES;

    for (int e = threadIdx.x; e < 128 * 64; e += 256) {
        const int m = e >> 6;
        const int k = e & 63;
        float v = 0.f;
        if (kind == 0) {
            v = (m < 64)
              ? g_wnv[(size_t)(b * COUT + m)        * (CIN * KTAPS) + k * KTAPS + t]
              : g_dwv[(size_t)(b * COUT + (m - 64)) * (CIN * KTAPS) + k * KTAPS + t];
        } else if (m >= 64) {
            v = g_wnv[(size_t)(b * COUT + (m - 64)) * (CIN * KTAPS) + k * KTAPS + t];
        }
        const uint32_t off = (uint32_t)(m * 128 + (((k >> 3) ^ (m & 7)) << 4) + (k & 7) * 2);
        *(__half*)(dst + off) = __float2half_rn(v);
    }
}

// ---------------------------------------------------------------------------
// Transpose NCDHW -> fp16 channel-last [b][z][y][x][c].
// ---------------------------------------------------------------------------
__global__ void transpose_kernel(const float* __restrict__ x, const float* __restrict__ dx)
{
    __shared__ float tile[64][65];
    const int tx = threadIdx.x;            // 0..31
    const int ty = threadIdx.y;            // 0..7
    const int y = blockIdx.x, z = blockIdx.y, b = blockIdx.z;

    const size_t in_base = (size_t)(b * 64) * 262144 + (size_t)z * 4096 + (size_t)y * 64;
    const size_t r0 = (((size_t)(b * 64 + z)) * 64 + y) * 64;

    const float* srcs[2] = { x, dx };
    __half* dsts[2] = { g_xTh, g_dxTh };

    for (int pass = 0; pass < 2; pass++) {
        const float* src = srcs[pass];
        __half* dst = dsts[pass];
        __syncthreads();
        for (int c = ty; c < 64; c += 8) {
            tile[c][tx]      = src[in_base + (size_t)c * 262144 + tx];
            tile[c][tx + 32] = src[in_base + (size_t)c * 262144 + tx + 32];
        }
        __syncthreads();
        for (int xr = ty; xr < 64; xr += 8) {
            dst[(r0 + xr) * 64 + tx]      = __float2half_rn(tile[tx][xr]);
            dst[(r0 + xr) * 64 + tx + 32] = __float2half_rn(tile[tx + 32][xr]);
        }
    }
}

// ---------------------------------------------------------------------------
// Conv implicit-GEMM, fp16 mma.sync m16n8k16 + ldmatrix, 2 CTAs/SM.
// CTA tile M=128 x N=128, 256 threads = 8 warps.
//  x-chunks (c<27):  warps 2M x 4N, warp m64 x n32, full M=128 tile.
//  dx-chunks (c>=27): ALL 8 warps compute dy rows (m64..127), each a distinct
//    n16 slice (n16 = wn*32 + wm*16) into dxacc -> balanced critical path.
// Epilogue merges dxacc (via padded smem exchange) into the dy outputs.
// Grid (31 ytiles, 62 z, 2 b) = 3844 CTAs -> 296 concurrent, ~13 even waves.
// ---------------------------------------------------------------------------
__global__ __launch_bounds__(256, 2) void conv_mma_kernel(
    const float* __restrict__ bias, float* __restrict__ out)
{
    extern __shared__ __align__(16) char smem[];
    const uint32_t sb = smem_u32(smem);

    const int tid = threadIdx.x;
    const int wid = tid >> 5;
    const int lid = tid & 31;
    const int wm  = wid >> 2;          // M tile 0..1 (x phase), n16-half (dx phase)
    const int wn  = wid & 3;           // N tile 0..3 (cols wn*32..)
    const int g   = lid >> 2;          // 0..7
    const int ct  = lid & 3;           // 0..3

    const int y0 = blockIdx.x * 2;     // 2 output rows per CTA (62 = 31*2)
    const int z0 = blockIdx.y;
    const int b  = blockIdx.z;

    float acc[4][4][4];
    #pragma unroll
    for (int mi = 0; mi < 4; ++mi)
        #pragma unroll
        for (int ni = 0; ni < 4; ++ni)
            #pragma unroll
            for (int j = 0; j < 4; ++j) acc[mi][ni][j] = 0.f;

    // ---- per-thread ldmatrix row indices ----
    const int a_row = (lid & 7) + ((lid >> 3) & 1) * 8;
    const int a_m   = wm * 64 + a_row;             // x phase, + mi*16
    const int a_mdx = 64 + a_row;                  // dx phase, + mi*16
    const int a_kq  = (lid >> 4) & 1;
    const int b_row = (lid & 7) + ((lid >> 4) & 1) * 8;
    const int b_n   = wn * 32 + b_row;             // x phase, + q*16
    const int b_ndx = wn * 32 + wm * 16 + b_row;   // dx phase (n16 slice)
    const int b_kq  = (lid >> 3) & 1;

    // ---- hoisted staging offsets (chunk-invariant) ----
    uint32_t bDst[4];
    uint32_t bSrc[4];
    #pragma unroll
    for (int it = 0; it < 4; ++it) {
        const int i  = tid + it * 256;     // 0..1023
        const int n  = i >> 3;             // 0..127
        const int c8 = i & 7;
        bDst[it] = (uint32_t)(A_BYTES + n * 128 + ((c8 ^ (n & 7)) << 4));
        bSrc[it] = (uint32_t)((((n >> 6) * 64 + (n & 63)) * 128) + c8 * 16);
    }
    const int rb0 = ((b * 64 + z0) * 64 + y0) * 64;
    const char* xB  = (const char*)g_xTh  + (size_t)rb0 * 128;
    const char* dxB = (const char*)g_dxTh + (size_t)rb0 * 128;
    const char* aBaseX  = (const char*)g_Ah + (size_t)(b * 2)     * KTAPS * A_BYTES;
    const char* aBaseDX = (const char*)g_Ah + (size_t)(b * 2 + 1) * KTAPS * A_BYTES;

    // ---- staging: chunk c into ring slot s ----
    auto stage = [&](int c, int s) {
        const int kind = (c >= KTAPS) ? 1 : 0;
        const int t    = c - (kind ? KTAPS : 0);
        const int dz   = t / 9;
        const int r1   = t - dz * 9;
        const int dyy  = r1 / 3;
        const int dxx  = r1 - dyy * 3;
        const uint32_t d = sb + s * STAGE;
        // A tile (pre-swizzled, linear copy); dx-chunks: rows 0..63 unused
        const char* srcA = (kind ? aBaseDX : aBaseX) + (size_t)t * A_BYTES;
        const uint32_t aOff = (uint32_t)tid * 16;
        if (!kind) {
            cp_async16(d + aOff,        srcA + aOff);
            cp_async16(d + aOff + 4096, srcA + aOff + 4096);
        }
        cp_async16(d + aOff + 8192,  srcA + aOff + 8192);
        cp_async16(d + aOff + 12288, srcA + aOff + 12288);
        // B tile: im2col gather with hoisted offsets (128 rows x 128B)
        const char* srcB = (kind ? dxB : xB) + (size_t)(dz * 4096 + dyy * 64 + dxx) * 128;
        #pragma unroll
        for (int it = 0; it < 4; ++it)
            cp_async16(d + bDst[it], srcB + bSrc[it]);
    };

    // ---- x-phase compute: warp m64 x n32, full M ----
    auto compute_x = [&](int s) {
        const uint32_t As = sb + s * STAGE;
        const uint32_t Bs = As + A_BYTES;
        #pragma unroll
        for (int ks = 0; ks < 4; ++ks) {
            const int kq_a = ks * 2 + a_kq;
            const int kq_b = ks * 2 + b_kq;
            uint32_t a[4][4];
            #pragma unroll
            for (int mi = 0; mi < 4; ++mi) {
                const int m = a_m + mi * 16;
                LDMATRIX_X4(a[mi][0], a[mi][1], a[mi][2], a[mi][3],
                            As + m * 128 + ((kq_a ^ (m & 7)) << 4));
            }
            uint32_t bq[2][4];
            #pragma unroll
            for (int q = 0; q < 2; ++q) {
                const int n = b_n + q * 16;
                LDMATRIX_X4(bq[q][0], bq[q][1], bq[q][2], bq[q][3],
                            Bs + n * 128 + ((kq_b ^ (n & 7)) << 4));
            }
            #pragma unroll
            for (int mi = 0; mi < 4; ++mi)
                #pragma unroll
                for (int q = 0; q < 2; ++q) {
                    mma_f16(acc[mi][2 * q + 0], a[mi], &bq[q][0]);
                    mma_f16(acc[mi][2 * q + 1], a[mi], &bq[q][2]);
                }
        }
    };

    // ---- prologue: fill 2 of 3 stages ----
    stage(0, 0); asm volatile("cp.async.commit_group;" ::: "memory");
    stage(1, 1); asm volatile("cp.async.commit_group;" ::: "memory");

    int s0i = 0;                        // slot of chunk c
    int s2i = 2;                        // slot of chunk c+2
    // ---- x-chunks: all 8 warps, full M ----
    for (int c = 0; c < KTAPS; ++c) {
        asm volatile("cp.async.wait_group %0;" :: "n"(NSTAGE - 2) : "memory");
        __syncthreads();
        stage(c + 2, s2i);              // c+2 <= 28 < 54, always valid
        asm volatile("cp.async.commit_group;" ::: "memory");
        compute_x(s0i);
        if (++s0i == NSTAGE) s0i = 0;
        if (++s2i == NSTAGE) s2i = 0;
    }

    // ---- dx-chunks: all 8 warps on dy rows, distinct n16 slices ----
    float dxacc[4][2][4];
    #pragma unroll
    for (int mi = 0; mi < 4; ++mi)
        #pragma unroll
        for (int q = 0; q < 2; ++q)
            #pragma unroll
            for (int j = 0; j < 4; ++j) dxacc[mi][q][j] = 0.f;

    for (int c = KTAPS; c < NCHUNK; ++c) {
        asm volatile("cp.async.wait_group %0;" :: "n"(NSTAGE - 2) : "memory");
        __syncthreads();
        if (c + 2 < NCHUNK) stage(c + 2, s2i);
        asm volatile("cp.async.commit_group;" ::: "memory");
        {
            const uint32_t As = sb + s0i * STAGE;
            const uint32_t Bs = As + A_BYTES;
            #pragma unroll
            for (int ks = 0; ks < 4; ++ks) {
                const int kq_a = ks * 2 + a_kq;
                const int kq_b = ks * 2 + b_kq;
                uint32_t a[4][4];
                #pragma unroll
                for (int mi = 0; mi < 4; ++mi) {
                    const int m = a_mdx + mi * 16;
                    LDMATRIX_X4(a[mi][0], a[mi][1], a[mi][2], a[mi][3],
                                As + m * 128 + ((kq_a ^ (m & 7)) << 4));
                }
                uint32_t bq[4];
                const int n = b_ndx;
                LDMATRIX_X4(bq[0], bq[1], bq[2], bq[3],
                            Bs + n * 128 + ((kq_b ^ (n & 7)) << 4));
                #pragma unroll
                for (int mi = 0; mi < 4; ++mi) {
                    mma_f16(dxacc[mi][0], a[mi], &bq[0]);
                    mma_f16(dxacc[mi][1], a[mi], &bq[2]);
                }
            }
        }
        if (++s0i == NSTAGE) s0i = 0;
        if (++s2i == NSTAGE) s2i = 0;
    }

    // ---- exchange dx partials through smem (disjoint n16 slices) ----
    __syncthreads();                   // everyone done reading the ring
    float* sdy = (float*)smem;         // 64 rows x SDY_STRIDE
    const int n16b = wn * 32 + wm * 16;
    #pragma unroll
    for (int mi = 0; mi < 4; ++mi)
        #pragma unroll
        for (int h = 0; h < 2; ++h) {
            const int ml = mi * 16 + h * 8 + g;
            #pragma unroll
            for (int q = 0; q < 2; ++q) {
                const int nn = n16b + q * 8 + ct * 2;
                sdy[ml * SDY_STRIDE + nn]     = dxacc[mi][q][h * 2 + 0];
                sdy[ml * SDY_STRIDE + nn + 1] = dxacc[mi][q][h * 2 + 1];
            }
        }
    __syncthreads();

    // ---- epilogue ----
    const size_t NOUT   = (size_t)DOUT * DOUT * DOUT;
    const size_t dy_off = (size_t)B_ * COUT * NOUT;
    const int m_base = wm * 64;
    const int n_base = wn * 32;

    #pragma unroll
    for (int mi = 0; mi < 4; ++mi) {
        #pragma unroll
        for (int h = 0; h < 2; ++h) {
            const int m  = m_base + mi * 16 + h * 8 + g;
            const bool isy = (m < 64);
            const int co = m & 63;
            const float bv = isy ? bias[co] : 0.f;
            const size_t outadd = isy ? 0 : dy_off;
            const size_t ob = ((size_t)(b * COUT + co) * DOUT + z0) * DOUT;
            #pragma unroll
            for (int ni = 0; ni < 4; ++ni) {
                const int n  = n_base + ni * 8 + ct * 2;
                const int yo = y0 + (n >> 6);       // < 62 always (31*2 grid)
                const int xo = n & 63;
                const size_t idx = (ob + yo) * DOUT + xo;
                if (xo < DOUT) {
                    float v0 = acc[mi][ni][h * 2 + 0] + bv;
                    float v1 = acc[mi][ni][h * 2 + 1] + bv;
                    if (!isy) {
                        v0 += sdy[(m - 64) * SDY_STRIDE + n];
                        v1 += sdy[(m - 64) * SDY_STRIDE + n + 1];
                    }
                    out[outadd + idx]     = v0;
                    out[outadd + idx + 1] = v1;     // xo even => xo+1 valid
                }
            }
        }
    }
}

// ---------------------------------------------------------------------------
// Launch. Inputs: x, s, dx, style_weight, style_bias, weight, bias.
// Output: concat(y, dy) fp32.
// ---------------------------------------------------------------------------
extern "C" void kernel_launch(void* const* d_in, const int* in_sizes, int n_in,
                              void* d_out, int out_size)
{
    const float* x    = (const float*)d_in[0];
    const float* s    = (const float*)d_in[1];
    const float* dx   = (const float*)d_in[2];
    const float* sw   = (const float*)d_in[3];
    const float* sb   = (const float*)d_in[4];
    const float* w    = (const float*)d_in[5];
    const float* bias = (const float*)d_in[6];
    float* out = (float*)d_out;

    cudaFuncSetAttribute(conv_mma_kernel, cudaFuncAttributeMaxDynamicSharedMemorySize, SMEM_DYN);

    prep_kernel<<<B_ * COUT, 256>>>(s, sw, sb, w);
    pack_kernel<<<B_ * 2 * KTAPS, 256>>>();
    transpose_kernel<<<dim3(64, 64, B_), dim3(32, 8)>>>(x, dx);
    conv_mma_kernel<<<dim3(31, 62, B_), 256, SMEM_DYN>>>(bias, out);
}